// round 12
// baseline (speedup 1.0000x reference)
#include <cuda_runtime.h>
#include <cuda_fp16.h>
#include <cuda_bf16.h>
#include <cstdint>

#define N_NODES 50000
#define N_EDGES 600000
#define N_GRAPHS 2048
#define EMB 128
#define N_LAYERS 3
#define ATOM_FEATS 9
#define ATOM_VOCAB 100
#define BOND_FEATS 3
#define BOND_VOCAB 8
#define BOND_DIM 3

#define CNT_PAD 53248   // 1024 threads * 52 (13 int4) >= N_NODES

// ---------------- scratch ----------------
__device__ __half g_hh[N_NODES * EMB];            // fp16 residual-carrying features
__device__ __half g_Z[(size_t)N_NODES * 3 * EMB];
__device__ float4 g_ewc[N_LAYERS * N_EDGES];
__device__ __half g_WT[N_LAYERS * EMB * 3 * EMB];
__device__ int    g_zero[CNT_PAD + N_GRAPHS * EMB + N_GRAPHS];  // cnt | gsum | gcnt
__device__ int    g_start[N_NODES + 1];
__device__ int    g_cursor[N_NODES];
__device__ int    g_csr_src[N_EDGES];

__device__ __forceinline__ uint32_t smem_u32(const void* p) {
    uint32_t a;
    asm("{ .reg .u64 t; cvta.to.shared.u64 t, %1; cvt.u32.u64 %0, t; }" : "=r"(a) : "l"(p));
    return a;
}

// ---------------- fused setup: atom encoder | degree count + gcnt | prepW ------
#define ATOM_BLOCKS 6250
#define CNT_BLOCKS 2344
#define PREPW_ELEMS (N_LAYERS * EMB * 3 * EMB)   // 147456
#define PREPW_BLOCKS ((PREPW_ELEMS + 255) / 256) // 576

__global__ void __launch_bounds__(256)
k_setup(const int* __restrict__ x, const float* __restrict__ aemb,
        __half* __restrict__ hh,
        const int* __restrict__ ei, const int* __restrict__ batch,
        int* __restrict__ cnt, float* __restrict__ gcnt,
        const float* __restrict__ W, __half* __restrict__ WT) {
    int bid = blockIdx.x;
    int tid = threadIdx.x;
    if (bid < ATOM_BLOCKS) {
        int n = bid * 8 + (tid >> 5);
        if (n >= N_NODES) return;
        int lane = tid & 31;
        int xv = 0;
        if (lane < ATOM_FEATS) xv = __ldg(&x[n * ATOM_FEATS + lane]);
        float4 s = make_float4(0.f, 0.f, 0.f, 0.f);
#pragma unroll
        for (int c = 0; c < ATOM_FEATS; c++) {
            int xc = __shfl_sync(0xffffffffu, xv, c);
            float4 v = *(const float4*)(aemb + ((size_t)(c * ATOM_VOCAB + xc)) * EMB + lane * 4);
            s.x += v.x; s.y += v.y; s.z += v.z; s.w += v.w;
        }
        size_t idx = (size_t)n * EMB + lane * 4;
        *(half2*)(hh + idx) = __floats2half2_rn(s.x, s.y);
        *(half2*)(hh + idx + 2) = __floats2half2_rn(s.z, s.w);
    } else if (bid < ATOM_BLOCKS + CNT_BLOCKS) {
        int i = (bid - ATOM_BLOCKS) * 256 + tid;
        if (i < N_EDGES) atomicAdd(&cnt[__ldg(&ei[N_EDGES + i])], 1);
        if (i < N_NODES) atomicAdd(&gcnt[__ldg(&batch[i])], 1.0f);
    } else {
        int idx = (bid - ATOM_BLOCKS - CNT_BLOCKS) * 256 + tid;
        if (idx >= PREPW_ELEMS) return;
        int bl = idx / 384;           // l*128 + j
        int t = idx - bl * 384;       // k*128 + i
        int l = bl >> 7, j = bl & 127;
        int k = t >> 7, i = t & 127;
        WT[idx] = __float2half(W[(((size_t)(l * BOND_DIM + k)) * EMB + i) * EMB + j]);
    }
}

// ---------------- scan (single block, vectorized loads) ----------------
__global__ void __launch_bounds__(1024)
k_scan(const int4* __restrict__ cnt4, int* __restrict__ start, int* __restrict__ cursor) {
    __shared__ int ssum[1024];
    int t = threadIdx.x;
    int vals[52];
    int s = 0;
#pragma unroll
    for (int i = 0; i < 13; i++) {
        int4 v = __ldg(&cnt4[t * 13 + i]);
        vals[i * 4 + 0] = v.x; vals[i * 4 + 1] = v.y;
        vals[i * 4 + 2] = v.z; vals[i * 4 + 3] = v.w;
        s += v.x + v.y + v.z + v.w;
    }
    ssum[t] = s;
    __syncthreads();
    for (int off = 1; off < 1024; off <<= 1) {
        int v = (t >= off) ? ssum[t - off] : 0;
        __syncthreads();
        ssum[t] += v;
        __syncthreads();
    }
    int run = ssum[t] - s;
#pragma unroll
    for (int i = 0; i < 52; i++) {
        int idx = t * 52 + i;
        if (idx < N_NODES) {
            start[idx] = run;
            cursor[idx] = run;
            run += vals[i];
        }
    }
    if (t == 0) start[N_NODES] = N_EDGES;
}

// ---------------- place + bond encoder fused ----------------
__global__ void k_place_bond(const int* __restrict__ ei, const int* __restrict__ ea,
                             const float* __restrict__ bemb, int* __restrict__ cursor,
                             int* __restrict__ csr_src, float4* __restrict__ ewc) {
    int e = blockIdx.x * blockDim.x + threadIdx.x;
    if (e >= N_EDGES) return;
    int d = ei[N_EDGES + e];
    int p = atomicAdd(&cursor[d], 1);
    csr_src[p] = ei[e];
    int a0 = ea[e * 3 + 0], a1 = ea[e * 3 + 1], a2 = ea[e * 3 + 2];
#pragma unroll
    for (int l = 0; l < N_LAYERS; l++) {
        const float* b0 = bemb + (((l * BOND_FEATS + 0) * BOND_VOCAB + a0) * BOND_DIM);
        const float* b1 = bemb + (((l * BOND_FEATS + 1) * BOND_VOCAB + a1) * BOND_DIM);
        const float* b2 = bemb + (((l * BOND_FEATS + 2) * BOND_VOCAB + a2) * BOND_DIM);
        float4 w;
        w.x = b0[0] + b1[0] + b2[0];
        w.y = b0[1] + b1[1] + b2[1];
        w.z = b0[2] + b1[2] + b2[2];
        w.w = 0.f;
        ewc[(size_t)l * N_EDGES + p] = w;
    }
}

// ---------------- aggregation v3: 1 node/warp, software-pipelined ----------
__global__ void __launch_bounds__(128)
k_aggz(const int* __restrict__ start, const int* __restrict__ csr_src,
       const float4* __restrict__ ewc, const __half* __restrict__ hh,
       __half* __restrict__ z) {
    int lane = threadIdx.x & 31;
    int d = blockIdx.x * 4 + (threadIdx.x >> 5);
    if (d >= N_NODES) return;
    int s = __ldg(&start[d]), e = __ldg(&start[d + 1]);
    int n = e - s;
    int nf = n & ~3;

    float a0[4] = {0, 0, 0, 0};
    float a1[4] = {0, 0, 0, 0};
    float a2[4] = {0, 0, 0, 0};

    int src[4];
    float4 w[4];
    if (nf > 0) {
#pragma unroll
        for (int i = 0; i < 4; i++) {
            src[i] = __ldg(&csr_src[s + i]);
            w[i]   = __ldg(&ewc[s + i]);
        }
    }
    for (int j = 0; j < nf; j += 4) {
        // gathers for current batch
        uint2 u[4];
#pragma unroll
        for (int i = 0; i < 4; i++)
            u[i] = __ldg((const uint2*)(hh + (size_t)src[i] * EMB + lane * 4));
        // prefetch next batch's edge data (uniform branch)
        int srcN[4];
        float4 wN[4];
        bool more = (j + 4) < nf;
        if (more) {
#pragma unroll
            for (int i = 0; i < 4; i++) {
                srcN[i] = __ldg(&csr_src[s + j + 4 + i]);
                wN[i]   = __ldg(&ewc[s + j + 4 + i]);
            }
        }
        // accumulate current batch
#pragma unroll
        for (int i = 0; i < 4; i++) {
            float2 p0 = __half22float2(*(const half2*)&u[i].x);
            float2 p1 = __half22float2(*(const half2*)&u[i].y);
            float hv[4] = {p0.x, p0.y, p1.x, p1.y};
#pragma unroll
            for (int q = 0; q < 4; q++) {
                a0[q] += w[i].x * hv[q];
                a1[q] += w[i].y * hv[q];
                a2[q] += w[i].z * hv[q];
            }
        }
        if (more) {
#pragma unroll
            for (int i = 0; i < 4; i++) { src[i] = srcN[i]; w[i] = wN[i]; }
        }
    }
    // remainder (<4 edges)
    for (int j = s + nf; j < e; j++) {
        int sc = __ldg(&csr_src[j]);
        float4 ww = __ldg(&ewc[j]);
        uint2 u = __ldg((const uint2*)(hh + (size_t)sc * EMB + lane * 4));
        float2 p0 = __half22float2(*(const half2*)&u.x);
        float2 p1 = __half22float2(*(const half2*)&u.y);
        float hv[4] = {p0.x, p0.y, p1.x, p1.y};
#pragma unroll
        for (int q = 0; q < 4; q++) {
            a0[q] += ww.x * hv[q];
            a1[q] += ww.y * hv[q];
            a2[q] += ww.z * hv[q];
        }
    }

    __half* zd = z + (size_t)d * 384 + lane * 4;
    uint2 o;
    half2* oh = (half2*)&o;
    oh[0] = __floats2half2_rn(a0[0], a0[1]);
    oh[1] = __floats2half2_rn(a0[2], a0[3]);
    *(uint2*)(zd) = o;
    oh[0] = __floats2half2_rn(a1[0], a1[1]);
    oh[1] = __floats2half2_rn(a1[2], a1[3]);
    *(uint2*)(zd + 128) = o;
    oh[0] = __floats2half2_rn(a2[0], a2[1]);
    oh[1] = __floats2half2_rn(a2[2], a2[3]);
    *(uint2*)(zd + 256) = o;
}

// ---------------- GEMM 64Mx128N + fp16-residual update (+ pooling last) --------
#define LDA 136
#define GBM 64

__global__ void __launch_bounds__(256, 2)
k_gemm_fused(const __half* __restrict__ Z, const __half* __restrict__ WT,
             const float* __restrict__ bl,
             __half* __restrict__ hh, int relu,
             const int* __restrict__ batch, float* __restrict__ gsum, int do_pool) {
    extern __shared__ __half sm[];
    __half* As = sm;                          // [64][LDA]
    __half* Bs = sm + GBM * LDA;              // [128][LDA]
    float* sbias = (float*)(sm + (GBM + 128) * LDA);
    const int M = N_NODES;
    int tid = threadIdx.x;
    int m0 = blockIdx.x * GBM;

    if (tid < 128) sbias[tid] = bl[tid] + bl[EMB + tid] + bl[2 * EMB + tid];

    int wid = tid >> 5, lane = tid & 31;
    int wm = wid & 3, wn = wid >> 2;          // 4 m x 2 n
    int mbase = wm * 16, nbase = wn * 64;     // warp tile 16 x 64

    float acc[8][4];
#pragma unroll
    for (int j = 0; j < 8; j++)
#pragma unroll
        for (int q = 0; q < 4; q++) acc[j][q] = 0.f;

#pragma unroll
    for (int kc = 0; kc < 3; kc++) {
        __syncthreads();
#pragma unroll
        for (int r = 0; r < 4; r++) {
            int lin = tid + r * 256;
            int row = lin >> 4;
            int col = (lin & 15) << 3;
            uint4 v = make_uint4(0u, 0u, 0u, 0u);
            int gm = m0 + row;
            if (gm < M) v = *(const uint4*)(Z + (size_t)gm * 384 + kc * 128 + col);
            *(uint4*)(As + row * LDA + col) = v;
        }
#pragma unroll
        for (int r = 0; r < 8; r++) {
            int lin = tid + r * 256;
            int row = lin >> 4;
            int col = (lin & 15) << 3;
            uint4 v = *(const uint4*)(WT + (size_t)row * 384 + kc * 128 + col);
            *(uint4*)(Bs + row * LDA + col) = v;
        }
        __syncthreads();

#pragma unroll
        for (int k16 = 0; k16 < 8; k16++) {
            int kk = k16 * 16;
            uint32_t a[4];
            {
                int row = mbase + (lane & 15);
                int col = kk + (lane >> 4) * 8;
                uint32_t addr = smem_u32(As + row * LDA + col);
                asm volatile("ldmatrix.sync.aligned.m8n8.x4.shared.b16 {%0,%1,%2,%3}, [%4];"
                             : "=r"(a[0]), "=r"(a[1]), "=r"(a[2]), "=r"(a[3])
                             : "r"(addr));
            }
            uint32_t bf[4][4];
#pragma unroll
            for (int j = 0; j < 4; j++) {
                int nrow = nbase + j * 16 + ((lane >> 4) << 3) + (lane & 7);
                int col = kk + (((lane >> 3) & 1) << 3);
                uint32_t addr = smem_u32(Bs + nrow * LDA + col);
                asm volatile("ldmatrix.sync.aligned.m8n8.x4.shared.b16 {%0,%1,%2,%3}, [%4];"
                             : "=r"(bf[j][0]), "=r"(bf[j][1]), "=r"(bf[j][2]), "=r"(bf[j][3])
                             : "r"(addr));
            }
#pragma unroll
            for (int jj = 0; jj < 8; jj++) {
                uint32_t b0 = bf[jj >> 1][(jj & 1) * 2 + 0];
                uint32_t b1 = bf[jj >> 1][(jj & 1) * 2 + 1];
                asm volatile(
                    "mma.sync.aligned.m16n8k16.row.col.f32.f16.f16.f32 "
                    "{%0,%1,%2,%3}, {%4,%5,%6,%7}, {%8,%9}, {%0,%1,%2,%3};"
                    : "+f"(acc[jj][0]), "+f"(acc[jj][1]),
                      "+f"(acc[jj][2]), "+f"(acc[jj][3])
                    : "r"(a[0]), "r"(a[1]), "r"(a[2]), "r"(a[3]),
                      "r"(b0), "r"(b1));
            }
        }
    }

    // ---- epilogue: v = act(acc + bias); new = v + float(hh_old); store fp16 ----
    {
        int row0 = m0 + mbase + (lane >> 2);
#pragma unroll
        for (int jj = 0; jj < 8; jj++) {
            int col = nbase + jj * 8 + 2 * (lane & 3);
            float b0 = sbias[col], b1 = sbias[col + 1];
#pragma unroll
            for (int half_row = 0; half_row < 2; half_row++) {
                int row = row0 + half_row * 8;
                if (row >= M) continue;
                float v0 = acc[jj][half_row * 2 + 0] + b0;
                float v1 = acc[jj][half_row * 2 + 1] + b1;
                if (relu) { v0 = fmaxf(v0, 0.f); v1 = fmaxf(v1, 0.f); }
                size_t idx = (size_t)row * EMB + col;
                float2 hof = __half22float2(*(const half2*)(hh + idx));
                float n0 = v0 + hof.x, n1 = v1 + hof.y;
                if (do_pool) {
                    int g = __ldg(&batch[row]);
                    float* gp = gsum + (size_t)g * EMB + col;
                    asm volatile("red.global.add.v2.f32 [%0], {%1, %2};"
                                 :: "l"(gp), "f"(n0), "f"(n1) : "memory");
                } else {
                    *(half2*)(hh + idx) = __floats2half2_rn(n0, n1);
                }
            }
        }
    }
}

// ---------------- final FCs ----------------
__global__ void k_final(const float* __restrict__ gsum, const float* __restrict__ gcnt,
                        const float* __restrict__ fc1_w, const float* __restrict__ fc1_b,
                        const float* __restrict__ fc2_w, const float* __restrict__ fc2_b,
                        float* __restrict__ out) {
    int g = blockIdx.x;
    int t = threadIdx.x;
    __shared__ float hg[EMB];
    __shared__ float red[EMB];
    float cnt = fmaxf(gcnt[g], 1.0f);
    hg[t] = gsum[(size_t)g * EMB + t] / cnt;
    __syncthreads();
    float z = fc1_b[t];
#pragma unroll 8
    for (int i = 0; i < EMB; i++) z += hg[i] * fc1_w[i * EMB + t];
    red[t] = z * fc2_w[t];
    __syncthreads();
    for (int s = 64; s > 0; s >>= 1) {
        if (t < s) red[t] += red[t + s];
        __syncthreads();
    }
    if (t == 0) out[g] = red[0] + fc2_b[0];
}

extern "C" void kernel_launch(void* const* d_in, const int* in_sizes, int n_in,
                              void* d_out, int out_size) {
    const int*   x     = (const int*)d_in[0];
    const int*   ei    = (const int*)d_in[1];
    const int*   ea    = (const int*)d_in[2];
    const int*   batch = (const int*)d_in[3];
    const float* aemb  = (const float*)d_in[4];
    const float* bemb  = (const float*)d_in[5];
    const float* W     = (const float*)d_in[6];
    const float* b     = (const float*)d_in[7];
    const float* fc1_w = (const float*)d_in[8];
    const float* fc1_b = (const float*)d_in[9];
    const float* fc2_w = (const float*)d_in[10];
    const float* fc2_b = (const float*)d_in[11];
    float* out = (float*)d_out;

    __half *hh, *Z, *WT;
    float4* ewc;
    int *zero_region, *start, *cursor, *csr_src;
    cudaGetSymbolAddress((void**)&hh, g_hh);
    cudaGetSymbolAddress((void**)&Z, g_Z);
    cudaGetSymbolAddress((void**)&ewc, g_ewc);
    cudaGetSymbolAddress((void**)&WT, g_WT);
    cudaGetSymbolAddress((void**)&zero_region, g_zero);
    cudaGetSymbolAddress((void**)&start, g_start);
    cudaGetSymbolAddress((void**)&cursor, g_cursor);
    cudaGetSymbolAddress((void**)&csr_src, g_csr_src);

    int* cnt = zero_region;
    float* gsum = (float*)(zero_region + CNT_PAD);
    float* gcnt = (float*)(zero_region + CNT_PAD + N_GRAPHS * EMB);

    const int smem_bytes = (GBM + 128) * LDA * sizeof(__half) + 128 * sizeof(float);
    cudaFuncSetAttribute(k_gemm_fused, cudaFuncAttributeMaxDynamicSharedMemorySize, smem_bytes);

    cudaMemsetAsync(zero_region, 0, (CNT_PAD + N_GRAPHS * EMB + N_GRAPHS) * sizeof(int));
    k_setup<<<ATOM_BLOCKS + CNT_BLOCKS + PREPW_BLOCKS, 256>>>(
        x, aemb, hh, ei, batch, cnt, gcnt, W, WT);
    k_scan<<<1, 1024>>>((const int4*)cnt, start, cursor);
    k_place_bond<<<(N_EDGES + 255) / 256, 256>>>(ei, ea, bemb, cursor, csr_src, ewc);

    for (int layer = 0; layer < N_LAYERS; layer++) {
        int last = (layer == N_LAYERS - 1);
        k_aggz<<<(N_NODES + 3) / 4, 128>>>(start, csr_src,
                                           ewc + (size_t)layer * N_EDGES, hh, Z);
        k_gemm_fused<<<(N_NODES + GBM - 1) / GBM, 256, smem_bytes>>>(
            Z, WT + (size_t)layer * EMB * 384, b + (size_t)layer * BOND_DIM * EMB,
            hh, layer < N_LAYERS - 1 ? 1 : 0,
            batch, gsum, last);
    }

    k_final<<<N_GRAPHS, EMB>>>(gsum, gcnt, fc1_w, fc1_b, fc2_w, fc2_b, out);
}

// round 13
// speedup vs baseline: 1.5821x; 1.5821x over previous
#include <cuda_runtime.h>
#include <cuda_fp16.h>
#include <cuda_bf16.h>
#include <cstdint>

#define N_NODES 50000
#define N_EDGES 600000
#define N_GRAPHS 2048
#define EMB 128
#define N_LAYERS 3
#define ATOM_FEATS 9
#define ATOM_VOCAB 100
#define BOND_FEATS 3
#define BOND_VOCAB 8
#define BOND_DIM 3

#define CNT_PAD 53248   // 1024 threads * 52 (13 int4) >= N_NODES

// ---------------- scratch ----------------
__device__ __half g_hh[N_NODES * EMB];            // fp16 residual-carrying features
__device__ __half g_Z[(size_t)N_NODES * 3 * EMB];
__device__ float4 g_ewc[N_LAYERS * N_EDGES];
__device__ __half g_WT[N_LAYERS * EMB * 3 * EMB];
__device__ int    g_zero[CNT_PAD + N_GRAPHS * EMB + N_GRAPHS];  // cnt | gsum | gcnt
__device__ int    g_start[N_NODES + 1];
__device__ int    g_cursor[N_NODES];
__device__ int    g_csr_src[N_EDGES];

__device__ __forceinline__ uint32_t smem_u32(const void* p) {
    uint32_t a;
    asm("{ .reg .u64 t; cvta.to.shared.u64 t, %1; cvt.u32.u64 %0, t; }" : "=r"(a) : "l"(p));
    return a;
}

// ---------------- fused setup: atom encoder | degree count + gcnt | prepW ------
#define ATOM_BLOCKS 6250
#define CNT_BLOCKS 2344
#define PREPW_ELEMS (N_LAYERS * EMB * 3 * EMB)   // 147456
#define PREPW_BLOCKS ((PREPW_ELEMS + 255) / 256) // 576

__global__ void __launch_bounds__(256)
k_setup(const int* __restrict__ x, const float* __restrict__ aemb,
        __half* __restrict__ hh,
        const int* __restrict__ ei, const int* __restrict__ batch,
        int* __restrict__ cnt, float* __restrict__ gcnt,
        const float* __restrict__ W, __half* __restrict__ WT) {
    int bid = blockIdx.x;
    int tid = threadIdx.x;
    if (bid < ATOM_BLOCKS) {
        int n = bid * 8 + (tid >> 5);
        if (n >= N_NODES) return;
        int lane = tid & 31;
        int xv = 0;
        if (lane < ATOM_FEATS) xv = __ldg(&x[n * ATOM_FEATS + lane]);
        float4 s = make_float4(0.f, 0.f, 0.f, 0.f);
#pragma unroll
        for (int c = 0; c < ATOM_FEATS; c++) {
            int xc = __shfl_sync(0xffffffffu, xv, c);
            float4 v = *(const float4*)(aemb + ((size_t)(c * ATOM_VOCAB + xc)) * EMB + lane * 4);
            s.x += v.x; s.y += v.y; s.z += v.z; s.w += v.w;
        }
        size_t idx = (size_t)n * EMB + lane * 4;
        *(half2*)(hh + idx) = __floats2half2_rn(s.x, s.y);
        *(half2*)(hh + idx + 2) = __floats2half2_rn(s.z, s.w);
    } else if (bid < ATOM_BLOCKS + CNT_BLOCKS) {
        int i = (bid - ATOM_BLOCKS) * 256 + tid;
        if (i < N_EDGES) atomicAdd(&cnt[__ldg(&ei[N_EDGES + i])], 1);
        if (i < N_NODES) atomicAdd(&gcnt[__ldg(&batch[i])], 1.0f);
    } else {
        int idx = (bid - ATOM_BLOCKS - CNT_BLOCKS) * 256 + tid;
        if (idx >= PREPW_ELEMS) return;
        int bl = idx / 384;           // l*128 + j
        int t = idx - bl * 384;       // k*128 + i
        int l = bl >> 7, j = bl & 127;
        int k = t >> 7, i = t & 127;
        WT[idx] = __float2half(W[(((size_t)(l * BOND_DIM + k)) * EMB + i) * EMB + j]);
    }
}

// ---------------- scan (single block, vectorized loads) ----------------
__global__ void __launch_bounds__(1024)
k_scan(const int4* __restrict__ cnt4, int* __restrict__ start, int* __restrict__ cursor) {
    __shared__ int ssum[1024];
    int t = threadIdx.x;
    int vals[52];
    int s = 0;
#pragma unroll
    for (int i = 0; i < 13; i++) {
        int4 v = __ldg(&cnt4[t * 13 + i]);
        vals[i * 4 + 0] = v.x; vals[i * 4 + 1] = v.y;
        vals[i * 4 + 2] = v.z; vals[i * 4 + 3] = v.w;
        s += v.x + v.y + v.z + v.w;
    }
    ssum[t] = s;
    __syncthreads();
    for (int off = 1; off < 1024; off <<= 1) {
        int v = (t >= off) ? ssum[t - off] : 0;
        __syncthreads();
        ssum[t] += v;
        __syncthreads();
    }
    int run = ssum[t] - s;
#pragma unroll
    for (int i = 0; i < 52; i++) {
        int idx = t * 52 + i;
        if (idx < N_NODES) {
            start[idx] = run;
            cursor[idx] = run;
            run += vals[i];
        }
    }
    if (t == 0) start[N_NODES] = N_EDGES;
}

// ---------------- place + bond encoder fused ----------------
__global__ void k_place_bond(const int* __restrict__ ei, const int* __restrict__ ea,
                             const float* __restrict__ bemb, int* __restrict__ cursor,
                             int* __restrict__ csr_src, float4* __restrict__ ewc) {
    int e = blockIdx.x * blockDim.x + threadIdx.x;
    if (e >= N_EDGES) return;
    int d = ei[N_EDGES + e];
    int p = atomicAdd(&cursor[d], 1);
    csr_src[p] = ei[e];
    int a0 = ea[e * 3 + 0], a1 = ea[e * 3 + 1], a2 = ea[e * 3 + 2];
#pragma unroll
    for (int l = 0; l < N_LAYERS; l++) {
        const float* b0 = bemb + (((l * BOND_FEATS + 0) * BOND_VOCAB + a0) * BOND_DIM);
        const float* b1 = bemb + (((l * BOND_FEATS + 1) * BOND_VOCAB + a1) * BOND_DIM);
        const float* b2 = bemb + (((l * BOND_FEATS + 2) * BOND_VOCAB + a2) * BOND_DIM);
        float4 w;
        w.x = b0[0] + b1[0] + b2[0];
        w.y = b0[1] + b1[1] + b2[1];
        w.z = b0[2] + b1[2] + b2[2];
        w.w = 0.f;
        ewc[(size_t)l * N_EDGES + p] = w;
    }
}

// ---------------- aggregation (R11 exact): 1 node/warp, 32 lanes x uint2 -------
__global__ void __launch_bounds__(128)
k_aggz(const int* __restrict__ start, const int* __restrict__ csr_src,
       const float4* __restrict__ ewc, const __half* __restrict__ hh,
       __half* __restrict__ z) {
    int lane = threadIdx.x & 31;
    int d = blockIdx.x * 4 + (threadIdx.x >> 5);
    if (d >= N_NODES) return;
    int s = __ldg(&start[d]), e = __ldg(&start[d + 1]);

    float a0[4] = {0, 0, 0, 0};
    float a1[4] = {0, 0, 0, 0};
    float a2[4] = {0, 0, 0, 0};

#define LOADG(i, jj) \
    int src##i = __ldg(&csr_src[(jj) + i]); \
    float4 w##i = __ldg(&ewc[(jj) + i]); \
    uint2 u##i = __ldg((const uint2*)(hh + (size_t)src##i * EMB + lane * 4));
#define ACC(i) do { \
    float2 p0 = __half22float2(*(const half2*)&u##i.x); \
    float2 p1 = __half22float2(*(const half2*)&u##i.y); \
    float hv[4] = {p0.x, p0.y, p1.x, p1.y}; \
    _Pragma("unroll") for (int q = 0; q < 4; q++) { \
        a0[q] += w##i.x * hv[q]; a1[q] += w##i.y * hv[q]; a2[q] += w##i.z * hv[q]; } \
    } while (0)

    int j = s;
    for (; j + 4 <= e; j += 4) {
        LOADG(0, j); LOADG(1, j); LOADG(2, j); LOADG(3, j);
        ACC(0); ACC(1); ACC(2); ACC(3);
    }
    for (; j < e; j++) {
        LOADG(0, j);
        ACC(0);
    }
#undef LOADG
#undef ACC

    __half* zd = z + (size_t)d * 384 + lane * 4;
    uint2 o;
    half2* oh = (half2*)&o;
    oh[0] = __floats2half2_rn(a0[0], a0[1]);
    oh[1] = __floats2half2_rn(a0[2], a0[3]);
    *(uint2*)(zd) = o;
    oh[0] = __floats2half2_rn(a1[0], a1[1]);
    oh[1] = __floats2half2_rn(a1[2], a1[3]);
    *(uint2*)(zd + 128) = o;
    oh[0] = __floats2half2_rn(a2[0], a2[1]);
    oh[1] = __floats2half2_rn(a2[2], a2[3]);
    *(uint2*)(zd + 256) = o;
}

// ---------------- GEMM 64Mx128N + fp16-residual update (+ pooling last) --------
#define LDA 136
#define GBM 64

__global__ void __launch_bounds__(256, 2)
k_gemm_fused(const __half* __restrict__ Z, const __half* __restrict__ WT,
             const float* __restrict__ bl,
             __half* __restrict__ hh, int relu,
             const int* __restrict__ batch, float* __restrict__ gsum, int do_pool) {
    extern __shared__ __half sm[];
    __half* As = sm;                          // [64][LDA]
    __half* Bs = sm + GBM * LDA;              // [128][LDA]
    float* sbias = (float*)(sm + (GBM + 128) * LDA);
    const int M = N_NODES;
    int tid = threadIdx.x;
    int m0 = blockIdx.x * GBM;

    if (tid < 128) sbias[tid] = bl[tid] + bl[EMB + tid] + bl[2 * EMB + tid];

    int wid = tid >> 5, lane = tid & 31;
    int wm = wid & 3, wn = wid >> 2;          // 4 m x 2 n
    int mbase = wm * 16, nbase = wn * 64;     // warp tile 16 x 64

    float acc[8][4];
#pragma unroll
    for (int j = 0; j < 8; j++)
#pragma unroll
        for (int q = 0; q < 4; q++) acc[j][q] = 0.f;

#pragma unroll
    for (int kc = 0; kc < 3; kc++) {
        __syncthreads();
#pragma unroll
        for (int r = 0; r < 4; r++) {
            int lin = tid + r * 256;
            int row = lin >> 4;
            int col = (lin & 15) << 3;
            uint4 v = make_uint4(0u, 0u, 0u, 0u);
            int gm = m0 + row;
            if (gm < M) v = *(const uint4*)(Z + (size_t)gm * 384 + kc * 128 + col);
            *(uint4*)(As + row * LDA + col) = v;
        }
#pragma unroll
        for (int r = 0; r < 8; r++) {
            int lin = tid + r * 256;
            int row = lin >> 4;
            int col = (lin & 15) << 3;
            uint4 v = *(const uint4*)(WT + (size_t)row * 384 + kc * 128 + col);
            *(uint4*)(Bs + row * LDA + col) = v;
        }
        __syncthreads();

#pragma unroll
        for (int k16 = 0; k16 < 8; k16++) {
            int kk = k16 * 16;
            uint32_t a[4];
            {
                int row = mbase + (lane & 15);
                int col = kk + (lane >> 4) * 8;
                uint32_t addr = smem_u32(As + row * LDA + col);
                asm volatile("ldmatrix.sync.aligned.m8n8.x4.shared.b16 {%0,%1,%2,%3}, [%4];"
                             : "=r"(a[0]), "=r"(a[1]), "=r"(a[2]), "=r"(a[3])
                             : "r"(addr));
            }
            uint32_t bf[4][4];
#pragma unroll
            for (int j = 0; j < 4; j++) {
                int nrow = nbase + j * 16 + ((lane >> 4) << 3) + (lane & 7);
                int col = kk + (((lane >> 3) & 1) << 3);
                uint32_t addr = smem_u32(Bs + nrow * LDA + col);
                asm volatile("ldmatrix.sync.aligned.m8n8.x4.shared.b16 {%0,%1,%2,%3}, [%4];"
                             : "=r"(bf[j][0]), "=r"(bf[j][1]), "=r"(bf[j][2]), "=r"(bf[j][3])
                             : "r"(addr));
            }
#pragma unroll
            for (int jj = 0; jj < 8; jj++) {
                uint32_t b0 = bf[jj >> 1][(jj & 1) * 2 + 0];
                uint32_t b1 = bf[jj >> 1][(jj & 1) * 2 + 1];
                asm volatile(
                    "mma.sync.aligned.m16n8k16.row.col.f32.f16.f16.f32 "
                    "{%0,%1,%2,%3}, {%4,%5,%6,%7}, {%8,%9}, {%0,%1,%2,%3};"
                    : "+f"(acc[jj][0]), "+f"(acc[jj][1]),
                      "+f"(acc[jj][2]), "+f"(acc[jj][3])
                    : "r"(a[0]), "r"(a[1]), "r"(a[2]), "r"(a[3]),
                      "r"(b0), "r"(b1));
            }
        }
    }

    // ---- epilogue: v = act(acc + bias); new = v + float(hh_old); store fp16 ----
    {
        int row0 = m0 + mbase + (lane >> 2);
#pragma unroll
        for (int jj = 0; jj < 8; jj++) {
            int col = nbase + jj * 8 + 2 * (lane & 3);
            float b0 = sbias[col], b1 = sbias[col + 1];
#pragma unroll
            for (int half_row = 0; half_row < 2; half_row++) {
                int row = row0 + half_row * 8;
                if (row >= M) continue;
                float v0 = acc[jj][half_row * 2 + 0] + b0;
                float v1 = acc[jj][half_row * 2 + 1] + b1;
                if (relu) { v0 = fmaxf(v0, 0.f); v1 = fmaxf(v1, 0.f); }
                size_t idx = (size_t)row * EMB + col;
                float2 hof = __half22float2(*(const half2*)(hh + idx));
                float n0 = v0 + hof.x, n1 = v1 + hof.y;
                if (do_pool) {
                    int g = __ldg(&batch[row]);
                    float* gp = gsum + (size_t)g * EMB + col;
                    asm volatile("red.global.add.v2.f32 [%0], {%1, %2};"
                                 :: "l"(gp), "f"(n0), "f"(n1) : "memory");
                } else {
                    *(half2*)(hh + idx) = __floats2half2_rn(n0, n1);
                }
            }
        }
    }
}

// ---------------- final FCs ----------------
__global__ void k_final(const float* __restrict__ gsum, const float* __restrict__ gcnt,
                        const float* __restrict__ fc1_w, const float* __restrict__ fc1_b,
                        const float* __restrict__ fc2_w, const float* __restrict__ fc2_b,
                        float* __restrict__ out) {
    int g = blockIdx.x;
    int t = threadIdx.x;
    __shared__ float hg[EMB];
    __shared__ float red[EMB];
    float cnt = fmaxf(gcnt[g], 1.0f);
    hg[t] = gsum[(size_t)g * EMB + t] / cnt;
    __syncthreads();
    float z = fc1_b[t];
#pragma unroll 8
    for (int i = 0; i < EMB; i++) z += hg[i] * fc1_w[i * EMB + t];
    red[t] = z * fc2_w[t];
    __syncthreads();
    for (int s = 64; s > 0; s >>= 1) {
        if (t < s) red[t] += red[t + s];
        __syncthreads();
    }
    if (t == 0) out[g] = red[0] + fc2_b[0];
}

extern "C" void kernel_launch(void* const* d_in, const int* in_sizes, int n_in,
                              void* d_out, int out_size) {
    const int*   x     = (const int*)d_in[0];
    const int*   ei    = (const int*)d_in[1];
    const int*   ea    = (const int*)d_in[2];
    const int*   batch = (const int*)d_in[3];
    const float* aemb  = (const float*)d_in[4];
    const float* bemb  = (const float*)d_in[5];
    const float* W     = (const float*)d_in[6];
    const float* b     = (const float*)d_in[7];
    const float* fc1_w = (const float*)d_in[8];
    const float* fc1_b = (const float*)d_in[9];
    const float* fc2_w = (const float*)d_in[10];
    const float* fc2_b = (const float*)d_in[11];
    float* out = (float*)d_out;

    __half *hh, *Z, *WT;
    float4* ewc;
    int *zero_region, *start, *cursor, *csr_src;
    cudaGetSymbolAddress((void**)&hh, g_hh);
    cudaGetSymbolAddress((void**)&Z, g_Z);
    cudaGetSymbolAddress((void**)&ewc, g_ewc);
    cudaGetSymbolAddress((void**)&WT, g_WT);
    cudaGetSymbolAddress((void**)&zero_region, g_zero);
    cudaGetSymbolAddress((void**)&start, g_start);
    cudaGetSymbolAddress((void**)&cursor, g_cursor);
    cudaGetSymbolAddress((void**)&csr_src, g_csr_src);

    int* cnt = zero_region;
    float* gsum = (float*)(zero_region + CNT_PAD);
    float* gcnt = (float*)(zero_region + CNT_PAD + N_GRAPHS * EMB);

    const int smem_bytes = (GBM + 128) * LDA * sizeof(__half) + 128 * sizeof(float);
    cudaFuncSetAttribute(k_gemm_fused, cudaFuncAttributeMaxDynamicSharedMemorySize, smem_bytes);

    cudaMemsetAsync(zero_region, 0, (CNT_PAD + N_GRAPHS * EMB + N_GRAPHS) * sizeof(int));
    k_setup<<<ATOM_BLOCKS + CNT_BLOCKS + PREPW_BLOCKS, 256>>>(
        x, aemb, hh, ei, batch, cnt, gcnt, W, WT);
    k_scan<<<1, 1024>>>((const int4*)cnt, start, cursor);
    k_place_bond<<<(N_EDGES + 255) / 256, 256>>>(ei, ea, bemb, cursor, csr_src, ewc);

    for (int layer = 0; layer < N_LAYERS; layer++) {
        int last = (layer == N_LAYERS - 1);
        k_aggz<<<(N_NODES + 3) / 4, 128>>>(start, csr_src,
                                           ewc + (size_t)layer * N_EDGES, hh, Z);
        k_gemm_fused<<<(N_NODES + GBM - 1) / GBM, 256, smem_bytes>>>(
            Z, WT + (size_t)layer * EMB * 384, b + (size_t)layer * BOND_DIM * EMB,
            hh, layer < N_LAYERS - 1 ? 1 : 0,
            batch, gsum, last);
    }

    k_final<<<N_GRAPHS, EMB>>>(gsum, gcnt, fc1_w, fc1_b, fc2_w, fc2_b, out);
}

// round 14
// speedup vs baseline: 1.6141x; 1.0203x over previous
#include <cuda_runtime.h>
#include <cuda_fp16.h>
#include <cuda_bf16.h>
#include <cstdint>

#define N_NODES 50000
#define N_EDGES 600000
#define N_GRAPHS 2048
#define EMB 128
#define N_LAYERS 3
#define ATOM_FEATS 9
#define ATOM_VOCAB 100
#define BOND_FEATS 3
#define BOND_VOCAB 8
#define BOND_DIM 3

#define CNT_PAD 53248   // 1024 threads * 52 (13 int4) >= N_NODES

#if defined(__CUDA_ARCH__) && __CUDA_ARCH__ >= 900
#define GRID_SYNC()   cudaGridDependencySynchronize()
#define PDL_TRIGGER() cudaTriggerProgrammaticLaunchCompletion()
#else
#define GRID_SYNC()
#define PDL_TRIGGER()
#endif

// ---------------- scratch ----------------
__device__ __half g_hh[N_NODES * EMB];            // fp16 residual-carrying features
__device__ __half g_Z[(size_t)N_NODES * 3 * EMB];
__device__ float4 g_ewc[N_LAYERS * N_EDGES];
__device__ __half g_WT[N_LAYERS * EMB * 3 * EMB];
__device__ int    g_zero[CNT_PAD + N_GRAPHS * EMB + N_GRAPHS];  // cnt | gsum | gcnt
__device__ int    g_start[N_NODES + 1];
__device__ int    g_cursor[N_NODES];
__device__ int    g_csr_src[N_EDGES];

__device__ __forceinline__ uint32_t smem_u32(const void* p) {
    uint32_t a;
    asm("{ .reg .u64 t; cvta.to.shared.u64 t, %1; cvt.u32.u64 %0, t; }" : "=r"(a) : "l"(p));
    return a;
}

// ---------------- fused setup: atom encoder | degree count + gcnt | prepW ------
#define ATOM_BLOCKS 6250
#define CNT_BLOCKS 2344
#define PREPW_ELEMS (N_LAYERS * EMB * 3 * EMB)   // 147456
#define PREPW_BLOCKS ((PREPW_ELEMS + 255) / 256) // 576

__global__ void __launch_bounds__(256)
k_setup(const int* __restrict__ x, const float* __restrict__ aemb,
        __half* __restrict__ hh,
        const int* __restrict__ ei, const int* __restrict__ batch,
        int* __restrict__ cnt, float* __restrict__ gcnt,
        const float* __restrict__ W, __half* __restrict__ WT) {
    PDL_TRIGGER();
    int bid = blockIdx.x;
    int tid = threadIdx.x;
    if (bid < ATOM_BLOCKS) {
        int n = bid * 8 + (tid >> 5);
        if (n >= N_NODES) return;
        int lane = tid & 31;
        int xv = 0;
        if (lane < ATOM_FEATS) xv = __ldg(&x[n * ATOM_FEATS + lane]);
        float4 s = make_float4(0.f, 0.f, 0.f, 0.f);
#pragma unroll
        for (int c = 0; c < ATOM_FEATS; c++) {
            int xc = __shfl_sync(0xffffffffu, xv, c);
            float4 v = *(const float4*)(aemb + ((size_t)(c * ATOM_VOCAB + xc)) * EMB + lane * 4);
            s.x += v.x; s.y += v.y; s.z += v.z; s.w += v.w;
        }
        size_t idx = (size_t)n * EMB + lane * 4;
        *(half2*)(hh + idx) = __floats2half2_rn(s.x, s.y);
        *(half2*)(hh + idx + 2) = __floats2half2_rn(s.z, s.w);
    } else if (bid < ATOM_BLOCKS + CNT_BLOCKS) {
        int i = (bid - ATOM_BLOCKS) * 256 + tid;
        if (i < N_EDGES) atomicAdd(&cnt[__ldg(&ei[N_EDGES + i])], 1);
        if (i < N_NODES) atomicAdd(&gcnt[__ldg(&batch[i])], 1.0f);
    } else {
        int idx = (bid - ATOM_BLOCKS - CNT_BLOCKS) * 256 + tid;
        if (idx >= PREPW_ELEMS) return;
        int bl = idx / 384;           // l*128 + j
        int t = idx - bl * 384;       // k*128 + i
        int l = bl >> 7, j = bl & 127;
        int k = t >> 7, i = t & 127;
        WT[idx] = __float2half(W[(((size_t)(l * BOND_DIM + k)) * EMB + i) * EMB + j]);
    }
}

// ---------------- scan (single block, vectorized loads) ----------------
__global__ void __launch_bounds__(1024)
k_scan(const int4* __restrict__ cnt4, int* __restrict__ start, int* __restrict__ cursor) {
    GRID_SYNC();
    PDL_TRIGGER();
    __shared__ int ssum[1024];
    int t = threadIdx.x;
    int vals[52];
    int s = 0;
#pragma unroll
    for (int i = 0; i < 13; i++) {
        int4 v = __ldg(&cnt4[t * 13 + i]);
        vals[i * 4 + 0] = v.x; vals[i * 4 + 1] = v.y;
        vals[i * 4 + 2] = v.z; vals[i * 4 + 3] = v.w;
        s += v.x + v.y + v.z + v.w;
    }
    ssum[t] = s;
    __syncthreads();
    for (int off = 1; off < 1024; off <<= 1) {
        int v = (t >= off) ? ssum[t - off] : 0;
        __syncthreads();
        ssum[t] += v;
        __syncthreads();
    }
    int run = ssum[t] - s;
#pragma unroll
    for (int i = 0; i < 52; i++) {
        int idx = t * 52 + i;
        if (idx < N_NODES) {
            start[idx] = run;
            cursor[idx] = run;
            run += vals[i];
        }
    }
    if (t == 0) start[N_NODES] = N_EDGES;
}

// ---------------- place + bond encoder fused ----------------
__global__ void k_place_bond(const int* __restrict__ ei, const int* __restrict__ ea,
                             const float* __restrict__ bemb, int* __restrict__ cursor,
                             int* __restrict__ csr_src, float4* __restrict__ ewc) {
    int e = blockIdx.x * blockDim.x + threadIdx.x;
    // loads independent of scan's output
    int d = 0, sv = 0, a0 = 0, a1 = 0, a2 = 0;
    if (e < N_EDGES) {
        d  = ei[N_EDGES + e];
        sv = ei[e];
        a0 = ea[e * 3 + 0]; a1 = ea[e * 3 + 1]; a2 = ea[e * 3 + 2];
    }
    GRID_SYNC();
    PDL_TRIGGER();
    if (e >= N_EDGES) return;
    int p = atomicAdd(&cursor[d], 1);
    csr_src[p] = sv;
#pragma unroll
    for (int l = 0; l < N_LAYERS; l++) {
        const float* b0 = bemb + (((l * BOND_FEATS + 0) * BOND_VOCAB + a0) * BOND_DIM);
        const float* b1 = bemb + (((l * BOND_FEATS + 1) * BOND_VOCAB + a1) * BOND_DIM);
        const float* b2 = bemb + (((l * BOND_FEATS + 2) * BOND_VOCAB + a2) * BOND_DIM);
        float4 w;
        w.x = b0[0] + b1[0] + b2[0];
        w.y = b0[1] + b1[1] + b2[1];
        w.z = b0[2] + b1[2] + b2[2];
        w.w = 0.f;
        ewc[(size_t)l * N_EDGES + p] = w;
    }
}

// ---------------- aggregation (R11 body): 1 node/warp, 32 lanes x uint2 --------
__global__ void __launch_bounds__(128)
k_aggz(const int* __restrict__ start, const int* __restrict__ csr_src,
       const float4* __restrict__ ewc, const __half* __restrict__ hh,
       __half* __restrict__ z) {
    GRID_SYNC();
    PDL_TRIGGER();
    int lane = threadIdx.x & 31;
    int d = blockIdx.x * 4 + (threadIdx.x >> 5);
    if (d >= N_NODES) return;
    int s = __ldg(&start[d]), e = __ldg(&start[d + 1]);

    float a0[4] = {0, 0, 0, 0};
    float a1[4] = {0, 0, 0, 0};
    float a2[4] = {0, 0, 0, 0};

#define LOADG(i, jj) \
    int src##i = __ldg(&csr_src[(jj) + i]); \
    float4 w##i = __ldg(&ewc[(jj) + i]); \
    uint2 u##i = __ldg((const uint2*)(hh + (size_t)src##i * EMB + lane * 4));
#define ACC(i) do { \
    float2 p0 = __half22float2(*(const half2*)&u##i.x); \
    float2 p1 = __half22float2(*(const half2*)&u##i.y); \
    float hv[4] = {p0.x, p0.y, p1.x, p1.y}; \
    _Pragma("unroll") for (int q = 0; q < 4; q++) { \
        a0[q] += w##i.x * hv[q]; a1[q] += w##i.y * hv[q]; a2[q] += w##i.z * hv[q]; } \
    } while (0)

    int j = s;
    for (; j + 4 <= e; j += 4) {
        LOADG(0, j); LOADG(1, j); LOADG(2, j); LOADG(3, j);
        ACC(0); ACC(1); ACC(2); ACC(3);
    }
    for (; j < e; j++) {
        LOADG(0, j);
        ACC(0);
    }
#undef LOADG
#undef ACC

    __half* zd = z + (size_t)d * 384 + lane * 4;
    uint2 o;
    half2* oh = (half2*)&o;
    oh[0] = __floats2half2_rn(a0[0], a0[1]);
    oh[1] = __floats2half2_rn(a0[2], a0[3]);
    *(uint2*)(zd) = o;
    oh[0] = __floats2half2_rn(a1[0], a1[1]);
    oh[1] = __floats2half2_rn(a1[2], a1[3]);
    *(uint2*)(zd + 128) = o;
    oh[0] = __floats2half2_rn(a2[0], a2[1]);
    oh[1] = __floats2half2_rn(a2[2], a2[3]);
    *(uint2*)(zd + 256) = o;
}

// ---------------- GEMM 64Mx128N + fp16-residual update (+ pooling last) --------
#define LDA 136
#define GBM 64

__global__ void __launch_bounds__(256, 2)
k_gemm_fused(const __half* __restrict__ Z, const __half* __restrict__ WT,
             const float* __restrict__ bl,
             __half* __restrict__ hh, int relu,
             const int* __restrict__ batch, float* __restrict__ gsum, int do_pool) {
    extern __shared__ __half sm[];
    __half* As = sm;                          // [64][LDA]
    __half* Bs = sm + GBM * LDA;              // [128][LDA]
    float* sbias = (float*)(sm + (GBM + 128) * LDA);
    const int M = N_NODES;
    int tid = threadIdx.x;
    int m0 = blockIdx.x * GBM;

    // bias + B chunk 0 are independent of the predecessor (WT/bl are setup-time)
    if (tid < 128) sbias[tid] = bl[tid] + bl[EMB + tid] + bl[2 * EMB + tid];

    int wid = tid >> 5, lane = tid & 31;
    int wm = wid & 3, wn = wid >> 2;          // 4 m x 2 n
    int mbase = wm * 16, nbase = wn * 64;     // warp tile 16 x 64

    float acc[8][4];
#pragma unroll
    for (int j = 0; j < 8; j++)
#pragma unroll
        for (int q = 0; q < 4; q++) acc[j][q] = 0.f;

#pragma unroll
    for (int kc = 0; kc < 3; kc++) {
        __syncthreads();
        // B chunk first (independent of Z)
#pragma unroll
        for (int r = 0; r < 8; r++) {
            int lin = tid + r * 256;
            int row = lin >> 4;
            int col = (lin & 15) << 3;
            uint4 v = *(const uint4*)(WT + (size_t)row * 384 + kc * 128 + col);
            *(uint4*)(Bs + row * LDA + col) = v;
        }
        if (kc == 0) {
            GRID_SYNC();       // wait for aggz's Z before first A load
            PDL_TRIGGER();
        }
        // A chunk (depends on Z)
#pragma unroll
        for (int r = 0; r < 4; r++) {
            int lin = tid + r * 256;
            int row = lin >> 4;
            int col = (lin & 15) << 3;
            uint4 v = make_uint4(0u, 0u, 0u, 0u);
            int gm = m0 + row;
            if (gm < M) v = *(const uint4*)(Z + (size_t)gm * 384 + kc * 128 + col);
            *(uint4*)(As + row * LDA + col) = v;
        }
        __syncthreads();

#pragma unroll
        for (int k16 = 0; k16 < 8; k16++) {
            int kk = k16 * 16;
            uint32_t a[4];
            {
                int row = mbase + (lane & 15);
                int col = kk + (lane >> 4) * 8;
                uint32_t addr = smem_u32(As + row * LDA + col);
                asm volatile("ldmatrix.sync.aligned.m8n8.x4.shared.b16 {%0,%1,%2,%3}, [%4];"
                             : "=r"(a[0]), "=r"(a[1]), "=r"(a[2]), "=r"(a[3])
                             : "r"(addr));
            }
            uint32_t bf[4][4];
#pragma unroll
            for (int j = 0; j < 4; j++) {
                int nrow = nbase + j * 16 + ((lane >> 4) << 3) + (lane & 7);
                int col = kk + (((lane >> 3) & 1) << 3);
                uint32_t addr = smem_u32(Bs + nrow * LDA + col);
                asm volatile("ldmatrix.sync.aligned.m8n8.x4.shared.b16 {%0,%1,%2,%3}, [%4];"
                             : "=r"(bf[j][0]), "=r"(bf[j][1]), "=r"(bf[j][2]), "=r"(bf[j][3])
                             : "r"(addr));
            }
#pragma unroll
            for (int jj = 0; jj < 8; jj++) {
                uint32_t b0 = bf[jj >> 1][(jj & 1) * 2 + 0];
                uint32_t b1 = bf[jj >> 1][(jj & 1) * 2 + 1];
                asm volatile(
                    "mma.sync.aligned.m16n8k16.row.col.f32.f16.f16.f32 "
                    "{%0,%1,%2,%3}, {%4,%5,%6,%7}, {%8,%9}, {%0,%1,%2,%3};"
                    : "+f"(acc[jj][0]), "+f"(acc[jj][1]),
                      "+f"(acc[jj][2]), "+f"(acc[jj][3])
                    : "r"(a[0]), "r"(a[1]), "r"(a[2]), "r"(a[3]),
                      "r"(b0), "r"(b1));
            }
        }
    }

    // ---- epilogue: v = act(acc + bias); new = v + float(hh_old); store fp16 ----
    {
        int row0 = m0 + mbase + (lane >> 2);
#pragma unroll
        for (int jj = 0; jj < 8; jj++) {
            int col = nbase + jj * 8 + 2 * (lane & 3);
            float b0 = sbias[col], b1 = sbias[col + 1];
#pragma unroll
            for (int half_row = 0; half_row < 2; half_row++) {
                int row = row0 + half_row * 8;
                if (row >= M) continue;
                float v0 = acc[jj][half_row * 2 + 0] + b0;
                float v1 = acc[jj][half_row * 2 + 1] + b1;
                if (relu) { v0 = fmaxf(v0, 0.f); v1 = fmaxf(v1, 0.f); }
                size_t idx = (size_t)row * EMB + col;
                float2 hof = __half22float2(*(const half2*)(hh + idx));
                float n0 = v0 + hof.x, n1 = v1 + hof.y;
                if (do_pool) {
                    int g = __ldg(&batch[row]);
                    float* gp = gsum + (size_t)g * EMB + col;
                    asm volatile("red.global.add.v2.f32 [%0], {%1, %2};"
                                 :: "l"(gp), "f"(n0), "f"(n1) : "memory");
                } else {
                    *(half2*)(hh + idx) = __floats2half2_rn(n0, n1);
                }
            }
        }
    }
}

// ---------------- final FCs ----------------
__global__ void k_final(const float* __restrict__ gsum, const float* __restrict__ gcnt,
                        const float* __restrict__ fc1_w, const float* __restrict__ fc1_b,
                        const float* __restrict__ fc2_w, const float* __restrict__ fc2_b,
                        float* __restrict__ out) {
    GRID_SYNC();
    int g = blockIdx.x;
    int t = threadIdx.x;
    __shared__ float hg[EMB];
    __shared__ float red[EMB];
    float cnt = fmaxf(gcnt[g], 1.0f);
    hg[t] = gsum[(size_t)g * EMB + t] / cnt;
    __syncthreads();
    float z = fc1_b[t];
#pragma unroll 8
    for (int i = 0; i < EMB; i++) z += hg[i] * fc1_w[i * EMB + t];
    red[t] = z * fc2_w[t];
    __syncthreads();
    for (int s = 64; s > 0; s >>= 1) {
        if (t < s) red[t] += red[t + s];
        __syncthreads();
    }
    if (t == 0) out[g] = red[0] + fc2_b[0];
}

extern "C" void kernel_launch(void* const* d_in, const int* in_sizes, int n_in,
                              void* d_out, int out_size) {
    const int*   x     = (const int*)d_in[0];
    const int*   ei    = (const int*)d_in[1];
    const int*   ea    = (const int*)d_in[2];
    const int*   batch = (const int*)d_in[3];
    const float* aemb  = (const float*)d_in[4];
    const float* bemb  = (const float*)d_in[5];
    const float* W     = (const float*)d_in[6];
    const float* b     = (const float*)d_in[7];
    const float* fc1_w = (const float*)d_in[8];
    const float* fc1_b = (const float*)d_in[9];
    const float* fc2_w = (const float*)d_in[10];
    const float* fc2_b = (const float*)d_in[11];
    float* out = (float*)d_out;

    __half *hh, *Z, *WT;
    float4* ewc;
    int *zero_region, *start, *cursor, *csr_src;
    cudaGetSymbolAddress((void**)&hh, g_hh);
    cudaGetSymbolAddress((void**)&Z, g_Z);
    cudaGetSymbolAddress((void**)&ewc, g_ewc);
    cudaGetSymbolAddress((void**)&WT, g_WT);
    cudaGetSymbolAddress((void**)&zero_region, g_zero);
    cudaGetSymbolAddress((void**)&start, g_start);
    cudaGetSymbolAddress((void**)&cursor, g_cursor);
    cudaGetSymbolAddress((void**)&csr_src, g_csr_src);

    int* cnt = zero_region;
    float* gsum = (float*)(zero_region + CNT_PAD);
    float* gcnt = (float*)(zero_region + CNT_PAD + N_GRAPHS * EMB);

    const int smem_bytes = (GBM + 128) * LDA * sizeof(__half) + 128 * sizeof(float);
    cudaFuncSetAttribute(k_gemm_fused, cudaFuncAttributeMaxDynamicSharedMemorySize, smem_bytes);

    // PDL launch attribute (secondary may pre-launch; device gridsync gates reads)
    cudaLaunchAttribute pdl[1];
    pdl[0].id = cudaLaunchAttributeProgrammaticStreamSerialization;
    pdl[0].val.programmaticStreamSerializationAllowed = 1;

    cudaMemsetAsync(zero_region, 0, (CNT_PAD + N_GRAPHS * EMB + N_GRAPHS) * sizeof(int));
    // setup follows a memset node: launch normally (no PDL edge to memset)
    k_setup<<<ATOM_BLOCKS + CNT_BLOCKS + PREPW_BLOCKS, 256>>>(
        x, aemb, hh, ei, batch, cnt, gcnt, W, WT);

    {
        cudaLaunchConfig_t cfg = {};
        cfg.gridDim = dim3(1); cfg.blockDim = dim3(1024);
        cfg.attrs = pdl; cfg.numAttrs = 1;
        cudaLaunchKernelEx(&cfg, k_scan, (const int4*)cnt, start, cursor);
    }
    {
        cudaLaunchConfig_t cfg = {};
        cfg.gridDim = dim3((N_EDGES + 255) / 256); cfg.blockDim = dim3(256);
        cfg.attrs = pdl; cfg.numAttrs = 1;
        cudaLaunchKernelEx(&cfg, k_place_bond, ei, ea, bemb, cursor, csr_src, ewc);
    }

    for (int layer = 0; layer < N_LAYERS; layer++) {
        int last = (layer == N_LAYERS - 1);
        {
            cudaLaunchConfig_t cfg = {};
            cfg.gridDim = dim3((N_NODES + 3) / 4); cfg.blockDim = dim3(128);
            cfg.attrs = pdl; cfg.numAttrs = 1;
            cudaLaunchKernelEx(&cfg, k_aggz,
                               (const int*)start, (const int*)csr_src,
                               (const float4*)(ewc + (size_t)layer * N_EDGES),
                               (const __half*)hh, Z);
        }
        {
            cudaLaunchConfig_t cfg = {};
            cfg.gridDim = dim3((N_NODES + GBM - 1) / GBM); cfg.blockDim = dim3(256);
            cfg.dynamicSmemBytes = smem_bytes;
            cfg.attrs = pdl; cfg.numAttrs = 1;
            cudaLaunchKernelEx(&cfg, k_gemm_fused,
                               (const __half*)Z,
                               (const __half*)(WT + (size_t)layer * EMB * 384),
                               (const float*)(b + (size_t)layer * BOND_DIM * EMB),
                               hh, (int)(layer < N_LAYERS - 1 ? 1 : 0),
                               batch, gsum, last);
        }
    }

    {
        cudaLaunchConfig_t cfg = {};
        cfg.gridDim = dim3(N_GRAPHS); cfg.blockDim = dim3(EMB);
        cfg.attrs = pdl; cfg.numAttrs = 1;
        cudaLaunchKernelEx(&cfg, k_final,
                           (const float*)gsum, (const float*)gcnt,
                           fc1_w, fc1_b, fc2_w, fc2_b, out);
    }
}

// round 15
// speedup vs baseline: 1.6999x; 1.0532x over previous
#include <cuda_runtime.h>
#include <cuda_fp16.h>
#include <cuda_bf16.h>
#include <cstdint>

#define N_NODES 50000
#define N_EDGES 600000
#define N_GRAPHS 2048
#define EMB 128
#define N_LAYERS 3
#define ATOM_FEATS 9
#define ATOM_VOCAB 100
#define BOND_FEATS 3
#define BOND_VOCAB 8
#define BOND_DIM 3

#define CNT_PAD 53248   // 1024 threads * 52 (13 int4) >= N_NODES
#define LUT_SIZE 512    // 8^3 attribute combinations

#if defined(__CUDA_ARCH__) && __CUDA_ARCH__ >= 900
#define GRID_SYNC()   cudaGridDependencySynchronize()
#define PDL_TRIGGER() cudaTriggerProgrammaticLaunchCompletion()
#else
#define GRID_SYNC()
#define PDL_TRIGGER()
#endif

// ---------------- scratch ----------------
__device__ __half g_hh[N_NODES * EMB];            // fp16 residual-carrying features
__device__ __half g_Z[(size_t)N_NODES * 3 * EMB];
__device__ float4 g_lut[N_LAYERS * LUT_SIZE];     // edge-weight LUT (24 KB total)
__device__ __half g_WT[N_LAYERS * EMB * 3 * EMB];
__device__ int    g_zero[CNT_PAD + N_GRAPHS * EMB + N_GRAPHS];  // cnt | gsum | gcnt
__device__ int    g_start[N_NODES + 1];
__device__ int    g_cursor[N_NODES];
__device__ int    g_csr[N_EDGES];                 // packed: src | attrs<<17

__device__ __forceinline__ uint32_t smem_u32(const void* p) {
    uint32_t a;
    asm("{ .reg .u64 t; cvta.to.shared.u64 t, %1; cvt.u32.u64 %0, t; }" : "=r"(a) : "l"(p));
    return a;
}

// ---------------- fused setup: atom | count+gcnt | prepW | ew-LUT ------
#define ATOM_BLOCKS 6250
#define CNT_BLOCKS 2344
#define PREPW_ELEMS (N_LAYERS * EMB * 3 * EMB)   // 147456
#define PREPW_BLOCKS ((PREPW_ELEMS + 255) / 256) // 576
#define LUT_ELEMS (N_LAYERS * LUT_SIZE)          // 1536
#define LUT_BLOCKS ((LUT_ELEMS + 255) / 256)     // 6

__global__ void __launch_bounds__(256)
k_setup(const int* __restrict__ x, const float* __restrict__ aemb,
        __half* __restrict__ hh,
        const int* __restrict__ ei, const int* __restrict__ batch,
        int* __restrict__ cnt, float* __restrict__ gcnt,
        const float* __restrict__ W, __half* __restrict__ WT,
        const float* __restrict__ bemb, float4* __restrict__ lut) {
    PDL_TRIGGER();
    int bid = blockIdx.x;
    int tid = threadIdx.x;
    if (bid < ATOM_BLOCKS) {
        int n = bid * 8 + (tid >> 5);
        if (n >= N_NODES) return;
        int lane = tid & 31;
        int xv = 0;
        if (lane < ATOM_FEATS) xv = __ldg(&x[n * ATOM_FEATS + lane]);
        float4 s = make_float4(0.f, 0.f, 0.f, 0.f);
#pragma unroll
        for (int c = 0; c < ATOM_FEATS; c++) {
            int xc = __shfl_sync(0xffffffffu, xv, c);
            float4 v = *(const float4*)(aemb + ((size_t)(c * ATOM_VOCAB + xc)) * EMB + lane * 4);
            s.x += v.x; s.y += v.y; s.z += v.z; s.w += v.w;
        }
        size_t idx = (size_t)n * EMB + lane * 4;
        *(half2*)(hh + idx) = __floats2half2_rn(s.x, s.y);
        *(half2*)(hh + idx + 2) = __floats2half2_rn(s.z, s.w);
    } else if (bid < ATOM_BLOCKS + CNT_BLOCKS) {
        int i = (bid - ATOM_BLOCKS) * 256 + tid;
        if (i < N_EDGES) atomicAdd(&cnt[__ldg(&ei[N_EDGES + i])], 1);
        if (i < N_NODES) atomicAdd(&gcnt[__ldg(&batch[i])], 1.0f);
    } else if (bid < ATOM_BLOCKS + CNT_BLOCKS + PREPW_BLOCKS) {
        int idx = (bid - ATOM_BLOCKS - CNT_BLOCKS) * 256 + tid;
        if (idx >= PREPW_ELEMS) return;
        int bl = idx / 384;           // l*128 + j
        int t = idx - bl * 384;       // k*128 + i
        int l = bl >> 7, j = bl & 127;
        int k = t >> 7, i = t & 127;
        WT[idx] = __float2half(W[(((size_t)(l * BOND_DIM + k)) * EMB + i) * EMB + j]);
    } else {
        int idx = (bid - ATOM_BLOCKS - CNT_BLOCKS - PREPW_BLOCKS) * 256 + tid;
        if (idx >= LUT_ELEMS) return;
        int l = idx >> 9;
        int code = idx & 511;
        int a0 = code & 7, a1 = (code >> 3) & 7, a2 = code >> 6;
        const float* b0 = bemb + (((l * BOND_FEATS + 0) * BOND_VOCAB + a0) * BOND_DIM);
        const float* b1 = bemb + (((l * BOND_FEATS + 1) * BOND_VOCAB + a1) * BOND_DIM);
        const float* b2 = bemb + (((l * BOND_FEATS + 2) * BOND_VOCAB + a2) * BOND_DIM);
        float4 w;
        w.x = b0[0] + b1[0] + b2[0];
        w.y = b0[1] + b1[1] + b2[1];
        w.z = b0[2] + b1[2] + b2[2];
        w.w = 0.f;
        lut[idx] = w;
    }
}

// ---------------- scan (single block, vectorized loads) ----------------
__global__ void __launch_bounds__(1024)
k_scan(const int4* __restrict__ cnt4, int* __restrict__ start, int* __restrict__ cursor) {
    GRID_SYNC();
    PDL_TRIGGER();
    __shared__ int ssum[1024];
    int t = threadIdx.x;
    int vals[52];
    int s = 0;
#pragma unroll
    for (int i = 0; i < 13; i++) {
        int4 v = __ldg(&cnt4[t * 13 + i]);
        vals[i * 4 + 0] = v.x; vals[i * 4 + 1] = v.y;
        vals[i * 4 + 2] = v.z; vals[i * 4 + 3] = v.w;
        s += v.x + v.y + v.z + v.w;
    }
    ssum[t] = s;
    __syncthreads();
    for (int off = 1; off < 1024; off <<= 1) {
        int v = (t >= off) ? ssum[t - off] : 0;
        __syncthreads();
        ssum[t] += v;
        __syncthreads();
    }
    int run = ssum[t] - s;
#pragma unroll
    for (int i = 0; i < 52; i++) {
        int idx = t * 52 + i;
        if (idx < N_NODES) {
            start[idx] = run;
            cursor[idx] = run;
            run += vals[i];
        }
    }
    if (t == 0) start[N_NODES] = N_EDGES;
}

// ---------------- place: CSR with packed src+attrs ----------------
__global__ void k_place(const int* __restrict__ ei, const int* __restrict__ ea,
                        int* __restrict__ cursor, int* __restrict__ csr) {
    int e = blockIdx.x * blockDim.x + threadIdx.x;
    int d = 0, packed = 0;
    if (e < N_EDGES) {
        d = ei[N_EDGES + e];
        int sv = ei[e];
        int a0 = ea[e * 3 + 0], a1 = ea[e * 3 + 1], a2 = ea[e * 3 + 2];
        packed = sv | (a0 << 17) | (a1 << 20) | (a2 << 23);
    }
    GRID_SYNC();
    PDL_TRIGGER();
    if (e >= N_EDGES) return;
    int p = atomicAdd(&cursor[d], 1);
    csr[p] = packed;
}

// ---------------- aggregation: 1 node/warp, LUT edge weights ----------
__global__ void __launch_bounds__(128)
k_aggz(const int* __restrict__ start, const int* __restrict__ csr,
       const float4* __restrict__ lut, const __half* __restrict__ hh,
       __half* __restrict__ z) {
    GRID_SYNC();
    PDL_TRIGGER();
    int lane = threadIdx.x & 31;
    int d = blockIdx.x * 4 + (threadIdx.x >> 5);
    if (d >= N_NODES) return;
    int s = __ldg(&start[d]), e = __ldg(&start[d + 1]);

    float a0[4] = {0, 0, 0, 0};
    float a1[4] = {0, 0, 0, 0};
    float a2[4] = {0, 0, 0, 0};

#define LOADG(i, jj) \
    int pk##i = __ldg(&csr[(jj) + i]); \
    float4 w##i = __ldg(&lut[(unsigned)pk##i >> 17]); \
    uint2 u##i = __ldg((const uint2*)(hh + (size_t)(pk##i & 0x1FFFF) * EMB + lane * 4));
#define ACC(i) do { \
    float2 p0 = __half22float2(*(const half2*)&u##i.x); \
    float2 p1 = __half22float2(*(const half2*)&u##i.y); \
    float hv[4] = {p0.x, p0.y, p1.x, p1.y}; \
    _Pragma("unroll") for (int q = 0; q < 4; q++) { \
        a0[q] += w##i.x * hv[q]; a1[q] += w##i.y * hv[q]; a2[q] += w##i.z * hv[q]; } \
    } while (0)

    int j = s;
    for (; j + 4 <= e; j += 4) {
        LOADG(0, j); LOADG(1, j); LOADG(2, j); LOADG(3, j);
        ACC(0); ACC(1); ACC(2); ACC(3);
    }
    for (; j < e; j++) {
        LOADG(0, j);
        ACC(0);
    }
#undef LOADG
#undef ACC

    __half* zd = z + (size_t)d * 384 + lane * 4;
    uint2 o;
    half2* oh = (half2*)&o;
    oh[0] = __floats2half2_rn(a0[0], a0[1]);
    oh[1] = __floats2half2_rn(a0[2], a0[3]);
    *(uint2*)(zd) = o;
    oh[0] = __floats2half2_rn(a1[0], a1[1]);
    oh[1] = __floats2half2_rn(a1[2], a1[3]);
    *(uint2*)(zd + 128) = o;
    oh[0] = __floats2half2_rn(a2[0], a2[1]);
    oh[1] = __floats2half2_rn(a2[2], a2[3]);
    *(uint2*)(zd + 256) = o;
}

// ---------------- GEMM 64Mx128N + fp16-residual update (+ pooling last) --------
#define LDA 136
#define GBM 64

__global__ void __launch_bounds__(256, 2)
k_gemm_fused(const __half* __restrict__ Z, const __half* __restrict__ WT,
             const float* __restrict__ bl,
             __half* __restrict__ hh, int relu,
             const int* __restrict__ batch, float* __restrict__ gsum, int do_pool) {
    extern __shared__ __half sm[];
    __half* As = sm;                          // [64][LDA]
    __half* Bs = sm + GBM * LDA;              // [128][LDA]
    float* sbias = (float*)(sm + (GBM + 128) * LDA);
    const int M = N_NODES;
    int tid = threadIdx.x;
    int m0 = blockIdx.x * GBM;

    if (tid < 128) sbias[tid] = bl[tid] + bl[EMB + tid] + bl[2 * EMB + tid];

    int wid = tid >> 5, lane = tid & 31;
    int wm = wid & 3, wn = wid >> 2;          // 4 m x 2 n
    int mbase = wm * 16, nbase = wn * 64;     // warp tile 16 x 64

    float acc[8][4];
#pragma unroll
    for (int j = 0; j < 8; j++)
#pragma unroll
        for (int q = 0; q < 4; q++) acc[j][q] = 0.f;

#pragma unroll
    for (int kc = 0; kc < 3; kc++) {
        __syncthreads();
        // B chunk first (independent of Z)
#pragma unroll
        for (int r = 0; r < 8; r++) {
            int lin = tid + r * 256;
            int row = lin >> 4;
            int col = (lin & 15) << 3;
            uint4 v = *(const uint4*)(WT + (size_t)row * 384 + kc * 128 + col);
            *(uint4*)(Bs + row * LDA + col) = v;
        }
        if (kc == 0) {
            GRID_SYNC();       // wait for aggz's Z before first A load
            PDL_TRIGGER();
        }
        // A chunk (depends on Z)
#pragma unroll
        for (int r = 0; r < 4; r++) {
            int lin = tid + r * 256;
            int row = lin >> 4;
            int col = (lin & 15) << 3;
            uint4 v = make_uint4(0u, 0u, 0u, 0u);
            int gm = m0 + row;
            if (gm < M) v = *(const uint4*)(Z + (size_t)gm * 384 + kc * 128 + col);
            *(uint4*)(As + row * LDA + col) = v;
        }
        __syncthreads();

#pragma unroll
        for (int k16 = 0; k16 < 8; k16++) {
            int kk = k16 * 16;
            uint32_t a[4];
            {
                int row = mbase + (lane & 15);
                int col = kk + (lane >> 4) * 8;
                uint32_t addr = smem_u32(As + row * LDA + col);
                asm volatile("ldmatrix.sync.aligned.m8n8.x4.shared.b16 {%0,%1,%2,%3}, [%4];"
                             : "=r"(a[0]), "=r"(a[1]), "=r"(a[2]), "=r"(a[3])
                             : "r"(addr));
            }
            uint32_t bf[4][4];
#pragma unroll
            for (int j = 0; j < 4; j++) {
                int nrow = nbase + j * 16 + ((lane >> 4) << 3) + (lane & 7);
                int col = kk + (((lane >> 3) & 1) << 3);
                uint32_t addr = smem_u32(Bs + nrow * LDA + col);
                asm volatile("ldmatrix.sync.aligned.m8n8.x4.shared.b16 {%0,%1,%2,%3}, [%4];"
                             : "=r"(bf[j][0]), "=r"(bf[j][1]), "=r"(bf[j][2]), "=r"(bf[j][3])
                             : "r"(addr));
            }
#pragma unroll
            for (int jj = 0; jj < 8; jj++) {
                uint32_t b0 = bf[jj >> 1][(jj & 1) * 2 + 0];
                uint32_t b1 = bf[jj >> 1][(jj & 1) * 2 + 1];
                asm volatile(
                    "mma.sync.aligned.m16n8k16.row.col.f32.f16.f16.f32 "
                    "{%0,%1,%2,%3}, {%4,%5,%6,%7}, {%8,%9}, {%0,%1,%2,%3};"
                    : "+f"(acc[jj][0]), "+f"(acc[jj][1]),
                      "+f"(acc[jj][2]), "+f"(acc[jj][3])
                    : "r"(a[0]), "r"(a[1]), "r"(a[2]), "r"(a[3]),
                      "r"(b0), "r"(b1));
            }
        }
    }

    // ---- epilogue: v = act(acc + bias); new = v + float(hh_old); store fp16 ----
    {
        int row0 = m0 + mbase + (lane >> 2);
#pragma unroll
        for (int jj = 0; jj < 8; jj++) {
            int col = nbase + jj * 8 + 2 * (lane & 3);
            float b0 = sbias[col], b1 = sbias[col + 1];
#pragma unroll
            for (int half_row = 0; half_row < 2; half_row++) {
                int row = row0 + half_row * 8;
                if (row >= M) continue;
                float v0 = acc[jj][half_row * 2 + 0] + b0;
                float v1 = acc[jj][half_row * 2 + 1] + b1;
                if (relu) { v0 = fmaxf(v0, 0.f); v1 = fmaxf(v1, 0.f); }
                size_t idx = (size_t)row * EMB + col;
                float2 hof = __half22float2(*(const half2*)(hh + idx));
                float n0 = v0 + hof.x, n1 = v1 + hof.y;
                if (do_pool) {
                    int g = __ldg(&batch[row]);
                    float* gp = gsum + (size_t)g * EMB + col;
                    asm volatile("red.global.add.v2.f32 [%0], {%1, %2};"
                                 :: "l"(gp), "f"(n0), "f"(n1) : "memory");
                } else {
                    *(half2*)(hh + idx) = __floats2half2_rn(n0, n1);
                }
            }
        }
    }
}

// ---------------- final FCs ----------------
__global__ void k_final(const float* __restrict__ gsum, const float* __restrict__ gcnt,
                        const float* __restrict__ fc1_w, const float* __restrict__ fc1_b,
                        const float* __restrict__ fc2_w, const float* __restrict__ fc2_b,
                        float* __restrict__ out) {
    GRID_SYNC();
    int g = blockIdx.x;
    int t = threadIdx.x;
    __shared__ float hg[EMB];
    __shared__ float red[EMB];
    float cnt = fmaxf(gcnt[g], 1.0f);
    hg[t] = gsum[(size_t)g * EMB + t] / cnt;
    __syncthreads();
    float z = fc1_b[t];
#pragma unroll 8
    for (int i = 0; i < EMB; i++) z += hg[i] * fc1_w[i * EMB + t];
    red[t] = z * fc2_w[t];
    __syncthreads();
    for (int s = 64; s > 0; s >>= 1) {
        if (t < s) red[t] += red[t + s];
        __syncthreads();
    }
    if (t == 0) out[g] = red[0] + fc2_b[0];
}

extern "C" void kernel_launch(void* const* d_in, const int* in_sizes, int n_in,
                              void* d_out, int out_size) {
    const int*   x     = (const int*)d_in[0];
    const int*   ei    = (const int*)d_in[1];
    const int*   ea    = (const int*)d_in[2];
    const int*   batch = (const int*)d_in[3];
    const float* aemb  = (const float*)d_in[4];
    const float* bemb  = (const float*)d_in[5];
    const float* W     = (const float*)d_in[6];
    const float* b     = (const float*)d_in[7];
    const float* fc1_w = (const float*)d_in[8];
    const float* fc1_b = (const float*)d_in[9];
    const float* fc2_w = (const float*)d_in[10];
    const float* fc2_b = (const float*)d_in[11];
    float* out = (float*)d_out;

    __half *hh, *Z, *WT;
    float4* lut;
    int *zero_region, *start, *cursor, *csr;
    cudaGetSymbolAddress((void**)&hh, g_hh);
    cudaGetSymbolAddress((void**)&Z, g_Z);
    cudaGetSymbolAddress((void**)&lut, g_lut);
    cudaGetSymbolAddress((void**)&WT, g_WT);
    cudaGetSymbolAddress((void**)&zero_region, g_zero);
    cudaGetSymbolAddress((void**)&start, g_start);
    cudaGetSymbolAddress((void**)&cursor, g_cursor);
    cudaGetSymbolAddress((void**)&csr, g_csr);

    int* cnt = zero_region;
    float* gsum = (float*)(zero_region + CNT_PAD);
    float* gcnt = (float*)(zero_region + CNT_PAD + N_GRAPHS * EMB);

    const int smem_bytes = (GBM + 128) * LDA * sizeof(__half) + 128 * sizeof(float);
    cudaFuncSetAttribute(k_gemm_fused, cudaFuncAttributeMaxDynamicSharedMemorySize, smem_bytes);

    cudaLaunchAttribute pdl[1];
    pdl[0].id = cudaLaunchAttributeProgrammaticStreamSerialization;
    pdl[0].val.programmaticStreamSerializationAllowed = 1;

    cudaMemsetAsync(zero_region, 0, (CNT_PAD + N_GRAPHS * EMB + N_GRAPHS) * sizeof(int));
    k_setup<<<ATOM_BLOCKS + CNT_BLOCKS + PREPW_BLOCKS + LUT_BLOCKS, 256>>>(
        x, aemb, hh, ei, batch, cnt, gcnt, W, WT, bemb, lut);

    {
        cudaLaunchConfig_t cfg = {};
        cfg.gridDim = dim3(1); cfg.blockDim = dim3(1024);
        cfg.attrs = pdl; cfg.numAttrs = 1;
        cudaLaunchKernelEx(&cfg, k_scan, (const int4*)cnt, start, cursor);
    }
    {
        cudaLaunchConfig_t cfg = {};
        cfg.gridDim = dim3((N_EDGES + 255) / 256); cfg.blockDim = dim3(256);
        cfg.attrs = pdl; cfg.numAttrs = 1;
        cudaLaunchKernelEx(&cfg, k_place, ei, ea, cursor, csr);
    }

    for (int layer = 0; layer < N_LAYERS; layer++) {
        int last = (layer == N_LAYERS - 1);
        {
            cudaLaunchConfig_t cfg = {};
            cfg.gridDim = dim3((N_NODES + 3) / 4); cfg.blockDim = dim3(128);
            cfg.attrs = pdl; cfg.numAttrs = 1;
            cudaLaunchKernelEx(&cfg, k_aggz,
                               (const int*)start, (const int*)csr,
                               (const float4*)(lut + (size_t)layer * LUT_SIZE),
                               (const __half*)hh, Z);
        }
        {
            cudaLaunchConfig_t cfg = {};
            cfg.gridDim = dim3((N_NODES + GBM - 1) / GBM); cfg.blockDim = dim3(256);
            cfg.dynamicSmemBytes = smem_bytes;
            cfg.attrs = pdl; cfg.numAttrs = 1;
            cudaLaunchKernelEx(&cfg, k_gemm_fused,
                               (const __half*)Z,
                               (const __half*)(WT + (size_t)layer * EMB * 384),
                               (const float*)(b + (size_t)layer * BOND_DIM * EMB),
                               hh, (int)(layer < N_LAYERS - 1 ? 1 : 0),
                               batch, gsum, last);
        }
    }

    {
        cudaLaunchConfig_t cfg = {};
        cfg.gridDim = dim3(N_GRAPHS); cfg.blockDim = dim3(EMB);
        cfg.attrs = pdl; cfg.numAttrs = 1;
        cudaLaunchKernelEx(&cfg, k_final,
                           (const float*)gsum, (const float*)gcnt,
                           fc1_w, fc1_b, fc2_w, fc2_b, out);
    }
}